// round 16
// baseline (speedup 1.0000x reference)
#include <cuda_runtime.h>
#include <cstdint>

#define BZf 8
#define Nf 4096
#define CFf 64
#define NSf 1024
#define Kf 64

typedef unsigned long long u64;

// ---------------- scratch (device globals; no allocation) ----------------
__device__ __align__(16) float g_W0f[67 * 64];
__device__ __align__(16) float g_b0f[64];
__device__ __align__(16) float g_W1d[64 * 64 * 2];      // [ci][cL][j dup x2]
__device__ __align__(16) float g_b1f[64];
__device__ __align__(16) float g_W2d[2 * 64 * 16 * 8];  // [half][ci][cL][j dup x2]
__device__ __align__(16) float g_b2f[128];
__device__ __align__(8) float g_pp[BZf * Nf];
__device__ __align__(16) float g_A[BZf * Nf * 64];  // 8 MB: per-point x·W0'[3:] + b0'
__device__ int   g_knn_idx[BZf * NSf * Kf];         // 2 MB
__device__ float g_knn_dist[BZf * NSf * Kf];        // 2 MB

// ---------------- packed fp32x2 helpers (sm_103a) ----------------
__device__ __forceinline__ void ffma2(u64& acc, u64 a, u64 b) {
    asm("fma.rn.f32x2 %0, %1, %2, %0;" : "+l"(acc) : "l"(a), "l"(b));
}
__device__ __forceinline__ u64 add2(u64 a, u64 b) {
    u64 r;
    asm("add.rn.f32x2 %0, %1, %2;" : "=l"(r) : "l"(a), "l"(b));
    return r;
}
__device__ __forceinline__ u64 mul2(u64 a, u64 b) {
    u64 r;
    asm("mul.rn.f32x2 %0, %1, %2;" : "=l"(r) : "l"(a), "l"(b));
    return r;
}
__device__ __forceinline__ u64 dup2(float v) {
    u64 r;
    unsigned int u = __float_as_uint(v);
    asm("mov.b64 %0, {%1, %1};" : "=l"(r) : "r"(u));
    return r;
}
__device__ __forceinline__ u64 pack2(float lo, float hi) {
    u64 r;
    asm("mov.b64 %0, {%1, %2};" : "=l"(r) : "f"(lo), "f"(hi));
    return r;
}
__device__ __forceinline__ float2 unpack2(u64 v) {
    float2 f;
    asm("mov.b64 {%0, %1}, %2;" : "=f"(f.x), "=f"(f.y) : "l"(v));
    return f;
}

// ---------------- prep: fold BN into (duplicated) weights + per-point norms ------------
__global__ void prep_kernel(const float* pos,
                            const float* W0, const float* b0, const float* gg0, const float* be0,
                            const float* rm0, const float* rv0,
                            const float* W1, const float* b1, const float* gg1, const float* be1,
                            const float* rm1, const float* rv1,
                            const float* W2, const float* b2, const float* gg2, const float* be2,
                            const float* rm2, const float* rv2) {
    int t = blockIdx.x * blockDim.x + threadIdx.x;
    int stride = gridDim.x * blockDim.x;
    for (int i = t; i < 67 * 64; i += stride) {
        int c = i & 63;
        float s = gg0[c] / sqrtf(rv0[c] + 1e-5f);
        g_W0f[i] = W0[i] * s;
    }
    for (int c = t; c < 64; c += stride) {
        float s = gg0[c] / sqrtf(rv0[c] + 1e-5f);
        g_b0f[c] = (b0[c] - rm0[c]) * s + be0[c];
    }
    for (int i = t; i < 64 * 64; i += stride) {
        int ci = i >> 6;
        int c = i & 63;
        float s = gg1[c] / sqrtf(rv1[c] + 1e-5f);
        float v = W1[i] * s;
        int cL = c >> 2, j = c & 3;
        int base = ((ci * 16 + cL) * 4 + j) * 2;
        g_W1d[base] = v;
        g_W1d[base + 1] = v;
    }
    for (int c = t; c < 64; c += stride) {
        float s = gg1[c] / sqrtf(rv1[c] + 1e-5f);
        g_b1f[c] = (b1[c] - rm1[c]) * s + be1[c];
    }
    for (int i = t; i < 64 * 128; i += stride) {
        int ci = i >> 7;
        int c = i & 127;
        float s = gg2[c] / sqrtf(rv2[c] + 1e-5f);
        float v = W2[i] * s;
        // c = cL*8 + half*4 + j  ->  duplicated pair layout
        int cL = c >> 3;
        int rem = c & 7;
        int half = rem >> 2;
        int j = rem & 3;
        int base = (((half * 64 + ci) * 16 + cL) * 4 + j) * 2;
        g_W2d[base] = v;
        g_W2d[base + 1] = v;
    }
    for (int c = t; c < 128; c += stride) {
        float s = gg2[c] / sqrtf(rv2[c] + 1e-5f);
        g_b2f[c] = (b2[c] - rm2[c]) * s + be2[c];
    }
    for (int i = t; i < BZf * Nf; i += stride) {
        float x = pos[i * 3], y = pos[i * 3 + 1], z = pos[i * 3 + 2];
        g_pp[i] = __fadd_rn(__fadd_rn(__fmul_rn(x, x), __fmul_rn(y, y)), __fmul_rn(z, z));
    }
}

// ---------------- FPS: packed f32x2 distances + REDUX argmax (exact ties) ----------
__global__ __launch_bounds__(1024) void fps_kernel(const float* pos, float* sampled) {
    extern __shared__ unsigned char fsm[];
    float* spx = (float*)fsm;                 // 4096
    float* spy = spx + Nf;                    // 4096
    float* spz = spy + Nf;                    // 4096
    u64* red = (u64*)(spz + Nf);              // 2*32

    int b = blockIdx.x;
    int t = threadIdx.x;
    int lane = t & 31;
    int w = t >> 5;
    float dist[4];
    u64 pxp[2], pyp[2], pzp[2];
    {
        float px[4], py[4], pz[4];
#pragma unroll
        for (int r = 0; r < 4; r++) {
            int i = t + (r << 10);
            const float* p = &pos[(b * Nf + i) * 3];
            float X = p[0], Y = p[1], Z = p[2];
            px[r] = X; py[r] = Y; pz[r] = Z;
            spx[i] = X; spy[i] = Y; spz[i] = Z;
            dist[r] = 1e10f;
        }
        pxp[0] = pack2(px[0], px[1]); pxp[1] = pack2(px[2], px[3]);
        pyp[0] = pack2(py[0], py[1]); pyp[1] = pack2(py[2], py[3]);
        pzp[0] = pack2(pz[0], pz[1]); pzp[1] = pack2(pz[2], pz[3]);
    }
    if (t == 0) {
        const float* p = &pos[b * Nf * 3];
        float* o = &sampled[b * NSf * 3];
        o[0] = p[0]; o[1] = p[1]; o[2] = p[2];
    }
    __syncthreads();
    float cx = spx[0], cy = spy[0], cz = spz[0];
    int parity = 0;

    for (int s = 0; s < NSf - 1; s++) {
        u64 ncx = dup2(-cx), ncy = dup2(-cy), ncz = dup2(-cz);
#pragma unroll
        for (int p = 0; p < 2; p++) {
            u64 dx = add2(pxp[p], ncx);
            u64 dy = add2(pyp[p], ncy);
            u64 dz = add2(pzp[p], ncz);
            u64 xx = mul2(dx, dx);
            u64 yy = mul2(dy, dy);
            u64 zz = mul2(dz, dz);
            u64 dd = add2(add2(xx, yy), zz);
            float2 f = unpack2(dd);
            dist[2 * p] = fminf(dist[2 * p], f.x);
            dist[2 * p + 1] = fminf(dist[2 * p + 1], f.y);
        }
        // max of nonneg floats == max of their bit patterns (alu pipe)
        unsigned int u0 = __float_as_uint(dist[0]), u1 = __float_as_uint(dist[1]);
        unsigned int u2 = __float_as_uint(dist[2]), u3 = __float_as_uint(dist[3]);
        unsigned int mb = max(max(u0, u1), max(u2, u3));
        unsigned int wm = __reduce_max_sync(0xffffffffu, mb);
        // first-match (lowest r) within the thread, ~idx-max across lanes -> global min idx
        unsigned int cand = 0u;
        if (u3 == wm) cand = ~(unsigned int)(t + 3072);
        if (u2 == wm) cand = ~(unsigned int)(t + 2048);
        if (u1 == wm) cand = ~(unsigned int)(t + 1024);
        if (u0 == wm) cand = ~(unsigned int)t;
        unsigned int wi = __reduce_max_sync(0xffffffffu, cand);
        if (lane == 0)
            red[parity * 32 + w] = ((u64)wm << 32) | (u64)wi;
        __syncthreads();
        u64 v = red[parity * 32 + lane];
        unsigned int d2 = (unsigned int)(v >> 32);
        unsigned int i2 = (unsigned int)v;
        unsigned int hi = __reduce_max_sync(0xffffffffu, d2);
        unsigned int c2 = (d2 == hi) ? i2 : 0u;
        unsigned int gi = __reduce_max_sync(0xffffffffu, c2);
        int nidx = (int)(~gi);
        cx = spx[nidx]; cy = spy[nidx]; cz = spz[nidx];
        if (t == 0) {
            float* o = &sampled[(b * NSf + s + 1) * 3];
            o[0] = cx; o[1] = cy; o[2] = cz;
        }
        parity ^= 1;
    }
}

// ---------------- merged precA + kNN (branch by block range) ----------------
#define PKA 2048  // precA blocks (16 rows each)
__global__ __launch_bounds__(256) void pk_kernel(const float* x, const float* pos,
                                                 const float* sampled) {
    extern __shared__ unsigned char smem[];
    int t = threadIdx.x;
    if (blockIdx.x < PKA) {
        // ---- precA: A = x . W0'[3:67] + b0', 16 rows per block ----
        float* sx = (float*)smem;  // 16*64
        int base = blockIdx.x * 16;
        for (int i = t; i < 16 * 64; i += 256) sx[i] = x[base * 64 + i];
        __syncthreads();
        int c = t & 63, rg = t >> 6;  // 4 row-groups x 4 rows
        float bv = g_b0f[c];
        float a0 = bv, a1 = bv, a2 = bv, a3 = bv;
        const float* sxr = &sx[rg * 4 * 64];
#pragma unroll 8
        for (int i = 0; i < 64; i++) {
            float wv = g_W0f[(3 + i) * 64 + c];
            a0 = fmaf(sxr[i], wv, a0);
            a1 = fmaf(sxr[64 + i], wv, a1);
            a2 = fmaf(sxr[128 + i], wv, a2);
            a3 = fmaf(sxr[192 + i], wv, a3);
        }
        int r0 = base + rg * 4;
        g_A[(r0 + 0) * 64 + c] = a0;
        g_A[(r0 + 1) * 64 + c] = a1;
        g_A[(r0 + 2) * 64 + c] = a2;
        g_A[(r0 + 3) * 64 + c] = a3;
        return;
    }
    // ---- kNN top-64: packed paired d^2, two passes (no sd buffer -> 6 blocks/SM) ----
    u64* cand = (u64*)smem;                         // 4096 u64 = 32KB
    int* scnt = (int*)(smem + 4096 * 8);            // 6 ints
    __shared__ float cxs, cys, czs, sss;
    int g = blockIdx.x - PKA;
    int b = g >> 10;
    if (t == 0) {
        float cx = sampled[g * 3], cy = sampled[g * 3 + 1], cz = sampled[g * 3 + 2];
        cxs = cx; cys = cy; czs = cz;
        sss = __fadd_rn(__fadd_rn(__fmul_rn(cx, cx), __fmul_rn(cy, cy)), __fmul_rn(cz, cz));
    }
    if (t < 6) scnt[t] = 0;
    __syncthreads();
    float sx = cxs, sy = cys, sz = czs, ss = sss;
    const float T0L = 0.18f * 0.18f * 0.99999f, T0H = 0.18f * 0.18f * 1.00001f;
    const float T1L = 0.25f * 0.25f * 0.99999f, T1H = 0.25f * 0.25f * 1.00001f;
    const float T2L = 0.35f * 0.35f * 0.99999f, T2H = 0.35f * 0.35f * 1.00001f;
    const float T3L = 0.55f * 0.55f * 0.99999f, T3H = 0.55f * 0.55f * 1.00001f;
    const float2* pb2 = (const float2*)&pos[b * Nf * 3];
    const float2* ppb2 = (const float2*)&g_pp[b * Nf];
    u64 sx2 = dup2(sx), sy2 = dup2(sy), sz2 = dup2(sz);
    u64 ss2 = dup2(ss), n2 = dup2(-2.0f);
    // pass 1: count (packed paired d^2; bit-exact vs reference formula)
    {
        int c0 = 0, c1 = 0, c2 = 0, c3 = 0;
        for (int q = t; q < Nf / 2; q += 256) {
            float2 q0 = pb2[3 * q];          // X0 Y0
            float2 q1 = pb2[3 * q + 1];      // Z0 X1
            float2 q2 = pb2[3 * q + 2];      // Y1 Z1
            u64 xs = pack2(q0.x, q1.y);
            u64 ys = pack2(q0.y, q2.x);
            u64 zs = pack2(q1.x, q2.y);
            float2 ppv = ppb2[q];
            u64 pp2 = pack2(ppv.x, ppv.y);
            u64 dot = add2(add2(mul2(sx2, xs), mul2(sy2, ys)), mul2(sz2, zs));
            u64 d2p = add2(add2(ss2, pp2), mul2(n2, dot));
            float2 dv = unpack2(d2p);
            c0 += (dv.x <= T0L) + (dv.y <= T0L);
            c1 += (dv.x <= T1L) + (dv.y <= T1L);
            c2 += (dv.x <= T2L) + (dv.y <= T2L);
            c3 += (dv.x <= T3L) + (dv.y <= T3L);
        }
        atomicAdd(&scnt[0], c0);
        atomicAdd(&scnt[1], c1);
        atomicAdd(&scnt[2], c2);
        atomicAdd(&scnt[3], c3);
    }
    __syncthreads();
    float thrsq;
    if (scnt[0] >= Kf) thrsq = T0H;
    else if (scnt[1] >= Kf) thrsq = T1H;
    else if (scnt[2] >= Kf) thrsq = T2H;
    else if (scnt[3] >= Kf) thrsq = T3H;
    else thrsq = 1e30f;
    // pass 2: recompute d^2 (identical ops -> identical bits) and collect survivors
    for (int q = t; q < Nf / 2; q += 256) {
        float2 q0 = pb2[3 * q];
        float2 q1 = pb2[3 * q + 1];
        float2 q2 = pb2[3 * q + 2];
        u64 xs = pack2(q0.x, q1.y);
        u64 ys = pack2(q0.y, q2.x);
        u64 zs = pack2(q1.x, q2.y);
        float2 ppv = ppb2[q];
        u64 pp2 = pack2(ppv.x, ppv.y);
        u64 dot = add2(add2(mul2(sx2, xs), mul2(sy2, ys)), mul2(sz2, zs));
        u64 d2p = add2(add2(ss2, pp2), mul2(n2, dot));
        float2 dv = unpack2(d2p);
        if (dv.x <= thrsq) {
            float d = sqrtf(fmaxf(dv.x, 0.0f));  // exact same expr as reference path
            int slot = atomicAdd(&scnt[5], 1);
            cand[slot] = ((u64)__float_as_uint(d) << 32) | (unsigned int)(2 * q);
        }
        if (dv.y <= thrsq) {
            float d = sqrtf(fmaxf(dv.y, 0.0f));
            int slot = atomicAdd(&scnt[5], 1);
            cand[slot] = ((u64)__float_as_uint(d) << 32) | (unsigned int)(2 * q + 1);
        }
    }
    __syncthreads();
    int cnt = scnt[5];
    int P = 128;
    while (P < cnt) P <<= 1;
    for (int i = t; i < P; i += 256)
        if (i >= cnt) cand[i] = 0xffffffffffffffffull;
    __syncthreads();
    for (int k2 = 2; k2 <= P; k2 <<= 1) {
        for (int j = k2 >> 1; j > 0; j >>= 1) {
            for (int i = t; i < P; i += 256) {
                int ij = i ^ j;
                if (ij > i) {
                    u64 a = cand[i], bb = cand[ij];
                    bool up = ((i & k2) == 0);
                    if ((a > bb) == up) { cand[i] = bb; cand[ij] = a; }
                }
            }
            __syncthreads();
        }
    }
    if (t < Kf) {
        u64 key = cand[t];
        g_knn_idx[g * Kf + t] = (int)(key & 0xffffffffull);
        g_knn_dist[g * Kf + t] = __uint_as_float((unsigned int)(key >> 32));
    }
}

// ---- fused MLP (FFMA2; pre-duplicated weights via LDG, no dup2 MOVs); 8 blocks/SM ----
#define AKS 68  // activation row stride ([c][k] layout), 16B-aligned rows
__global__ __launch_bounds__(128, 8) void mlp_kernel(const float* pos, const float* sampled,
                                                     float* out) {
    extern __shared__ unsigned char smem[];
    float* act = (float*)smem;             // 64*68 (layer1 out -> layer2 out -> pmax alias)
    float* sB1 = act + 64 * AKS;           // 64
    float* sB2 = sB1 + 64;                 // 128
    float* sdpx = sB2 + 128;               // 64
    float* sdpy = sdpx + 64;               // 64
    float* sdpz = sdpy + 64;               // 64
    int* sidx = (int*)(sdpz + 64);         // 64
    int* smask = sidx + 64;                // 64
    float* pmax = act;                     // 8*128, aliased into act after barrier

    int g = blockIdx.x;
    int b = g >> 10;
    int t = threadIdx.x;
    int w = t >> 5, lane = t & 31;
    int ksub = lane >> 4;                  // 0/1
    int k0 = w * 16 + ksub * 8;            // this thread's 8 k's (layers 2/3)
    int cL = lane & 15;

    if (t < 64) sB1[t] = g_b1f[t];
    if (t < 128) sB2[t] = g_b2f[t];
    if (t < 64) {
        int idx = g_knn_idx[g * Kf + t];
        float d = g_knn_dist[g * Kf + t];
        const float* p = &pos[(b * Nf + idx) * 3];
        float ccx = sampled[g * 3], ccy = sampled[g * 3 + 1], ccz = sampled[g * 3 + 2];
        sdpx[t] = p[0] - ccx;
        sdpy[t] = p[1] - ccy;
        sdpz[t] = p[2] - ccz;
        sidx[t] = idx;
        smask[t] = (d <= 0.2f) ? 1 : 0;
    }
    __syncthreads();

    // layer 1 (input 67 -> 64): thread owns (c, one 32-k half), even k-pairs.
    {
        int c = t & 63;
        int h = t >> 6;                    // 0/1
        int kb = h * 32;
        float w0 = g_W0f[c], w1 = g_W0f[64 + c], w2 = g_W0f[128 + c];
        const float* Ab = &g_A[(size_t)b * Nf * 64 + c];
#pragma unroll 4
        for (int i = 0; i < 16; i++) {
            int k = kb + 2 * i;
            int2 si = *(const int2*)&sidx[k];
            float a0 = Ab[si.x * 64];
            float a1 = Ab[si.y * 64];
            float2 dx2 = *(const float2*)&sdpx[k];
            float2 dy2 = *(const float2*)&sdpy[k];
            float2 dz2 = *(const float2*)&sdpz[k];
            float z0 = fmaf(dx2.x, w0, a0);
            z0 = fmaf(dy2.x, w1, z0);
            z0 = fmaf(dz2.x, w2, z0);
            float z1 = fmaf(dx2.y, w0, a1);
            z1 = fmaf(dy2.y, w1, z1);
            z1 = fmaf(dz2.y, w2, z1);
            float2 r;
            r.x = fmaxf(z0, 0.0f);
            r.y = fmaxf(z1, 0.0f);
            *(float2*)&act[c * AKS + k] = r;
        }
    }
    __syncthreads();

    // layer 2 (64 -> 64): thread tile 8k x 4c; duplicated W1 pairs via 2x LDG.128
    u64 acc2[4][4];
    {
        const ulonglong2* W1v = (const ulonglong2*)g_W1d;  // 4 u64-pairs per (ci,cL)
#pragma unroll
        for (int j = 0; j < 4; j++)
#pragma unroll
            for (int q = 0; q < 4; q++) acc2[j][q] = 0ull;
        for (int ci = 0; ci < 64; ci++) {
            ulonglong2 va = *(const ulonglong2*)&act[ci * AKS + k0];
            ulonglong2 vb = *(const ulonglong2*)&act[ci * AKS + k0 + 4];
            u64 a0 = va.x, a1 = va.y, a2 = vb.x, a3 = vb.y;
            ulonglong2 wA = __ldg(&W1v[(ci * 16 + cL) * 2]);
            ulonglong2 wB = __ldg(&W1v[(ci * 16 + cL) * 2 + 1]);
            u64 w0 = wA.x, w1 = wA.y, w2 = wB.x, w3 = wB.y;
            ffma2(acc2[0][0], a0, w0); ffma2(acc2[1][0], a1, w0);
            ffma2(acc2[2][0], a2, w0); ffma2(acc2[3][0], a3, w0);
            ffma2(acc2[0][1], a0, w1); ffma2(acc2[1][1], a1, w1);
            ffma2(acc2[2][1], a2, w1); ffma2(acc2[3][1], a3, w1);
            ffma2(acc2[0][2], a0, w2); ffma2(acc2[1][2], a1, w2);
            ffma2(acc2[2][2], a2, w2); ffma2(acc2[3][2], a3, w2);
            ffma2(acc2[0][3], a0, w3); ffma2(acc2[1][3], a1, w3);
            ffma2(acc2[2][3], a2, w3); ffma2(acc2[3][3], a3, w3);
        }
    }
    __syncthreads();  // all reads of layer-1 act done; safe to overwrite
    {
        int cc0 = cL * 4;
#pragma unroll
        for (int cq = 0; cq < 4; cq++) {
            float bb = sB1[cc0 + cq];
#pragma unroll
            for (int kp = 0; kp < 4; kp++) {
                float2 v = unpack2(acc2[kp][cq]);
                float2 r;
                r.x = fmaxf(v.x + bb, 0.0f);
                r.y = fmaxf(v.y + bb, 0.0f);
                *(float2*)&act[(cc0 + cq) * AKS + k0 + 2 * kp] = r;
            }
        }
    }
    __syncthreads();

    // layer 3 (64 -> 128) + masked max pool: two passes of 4 channels
    // duplicated W2 pairs via 2x LDG.128; act via ulonglong2
    float mres[8];
    const ulonglong2* W2v = (const ulonglong2*)g_W2d;  // 4 u64-pairs per (half,ci,cL)
#pragma unroll 1
    for (int half = 0; half < 2; half++) {
        int cc0 = cL * 8 + half * 4;
        u64 acc[4][4];
#pragma unroll
        for (int j = 0; j < 4; j++)
#pragma unroll
            for (int q = 0; q < 4; q++) acc[j][q] = 0ull;
#pragma unroll 2
        for (int ci = 0; ci < 64; ci++) {
            ulonglong2 va = *(const ulonglong2*)&act[ci * AKS + k0];
            ulonglong2 vb = *(const ulonglong2*)&act[ci * AKS + k0 + 4];
            u64 a0 = va.x, a1 = va.y, a2 = vb.x, a3 = vb.y;
            int wbase = ((half * 64 + ci) * 16 + cL) * 2;
            ulonglong2 wA = __ldg(&W2v[wbase]);
            ulonglong2 wB = __ldg(&W2v[wbase + 1]);
            u64 w0 = wA.x, w1 = wA.y, w2 = wB.x, w3 = wB.y;
            ffma2(acc[0][0], a0, w0); ffma2(acc[1][0], a1, w0);
            ffma2(acc[2][0], a2, w0); ffma2(acc[3][0], a3, w0);
            ffma2(acc[0][1], a0, w1); ffma2(acc[1][1], a1, w1);
            ffma2(acc[2][1], a2, w1); ffma2(acc[3][1], a3, w1);
            ffma2(acc[0][2], a0, w2); ffma2(acc[1][2], a1, w2);
            ffma2(acc[2][2], a2, w2); ffma2(acc[3][2], a3, w2);
            ffma2(acc[0][3], a0, w3); ffma2(acc[1][3], a1, w3);
            ffma2(acc[2][3], a2, w3); ffma2(acc[3][3], a3, w3);
        }
#pragma unroll
        for (int cq = 0; cq < 4; cq++) {
            float bb = sB2[cc0 + cq];
            float m = -1e8f;
#pragma unroll
            for (int kp = 0; kp < 4; kp++) {
                float2 v = unpack2(acc[kp][cq]);
                float h0 = fmaxf(v.x + bb, 0.0f);
                float h1 = fmaxf(v.y + bb, 0.0f);
                float q0 = smask[k0 + 2 * kp] ? h0 : -1e8f;
                float q1 = smask[k0 + 2 * kp + 1] ? h1 : -1e8f;
                m = fmaxf(m, fmaxf(q0, q1));
            }
            mres[half * 4 + cq] = m;
        }
    }
    __syncthreads();  // all act reads done; alias pmax onto act
    {
        int base = (w * 2 + ksub) * 128 + cL * 8;
#pragma unroll
        for (int q = 0; q < 8; q++) pmax[base + q] = mres[q];
    }
    __syncthreads();
    if (t < 128) {
        float m = pmax[t];
#pragma unroll
        for (int q = 1; q < 8; q++) m = fmaxf(m, pmax[q * 128 + t]);
        out[g * 128 + t] = m;
    }
}

// ---------------- launch ----------------
extern "C" void kernel_launch(void* const* d_in, const int* in_sizes, int n_in,
                              void* d_out, int out_size) {
    (void)in_sizes; (void)n_in; (void)out_size;
    const float* x = (const float*)d_in[0];
    const float* pos = (const float*)d_in[1];
    const float* W0 = (const float*)d_in[2];
    const float* b0 = (const float*)d_in[3];
    const float* gg0 = (const float*)d_in[4];
    const float* be0 = (const float*)d_in[5];
    const float* rm0 = (const float*)d_in[6];
    const float* rv0 = (const float*)d_in[7];
    const float* W1 = (const float*)d_in[8];
    const float* b1 = (const float*)d_in[9];
    const float* gg1 = (const float*)d_in[10];
    const float* be1 = (const float*)d_in[11];
    const float* rm1 = (const float*)d_in[12];
    const float* rv1 = (const float*)d_in[13];
    const float* W2 = (const float*)d_in[14];
    const float* b2 = (const float*)d_in[15];
    const float* gg2 = (const float*)d_in[16];
    const float* be2 = (const float*)d_in[17];
    const float* rm2 = (const float*)d_in[18];
    const float* rv2 = (const float*)d_in[19];

    float* out = (float*)d_out;
    float* sampled = out + (size_t)BZf * NSf * 128;

    const int pk_smem = 4096 * 8 + 32;              // 32800 -> 6 blocks/SM
    const int mlp_smem = (64 * AKS + 64 + 128 + 64 * 5) * 4;  // 19456
    const int fps_smem = Nf * 3 * 4 + 2 * 32 * 8;   // 49664
    cudaFuncSetAttribute(pk_kernel, cudaFuncAttributeMaxDynamicSharedMemorySize, pk_smem);
    cudaFuncSetAttribute(mlp_kernel, cudaFuncAttributeMaxDynamicSharedMemorySize, mlp_smem);
    cudaFuncSetAttribute(fps_kernel, cudaFuncAttributeMaxDynamicSharedMemorySize, fps_smem);

    prep_kernel<<<64, 256>>>(pos,
                             W0, b0, gg0, be0, rm0, rv0,
                             W1, b1, gg1, be1, rm1, rv1,
                             W2, b2, gg2, be2, rm2, rv2);
    fps_kernel<<<BZf, 1024, fps_smem>>>(pos, sampled);
    pk_kernel<<<PKA + BZf * NSf, 256, pk_smem>>>(x, pos, sampled);
    mlp_kernel<<<BZf * NSf, 128, mlp_smem>>>(pos, sampled, out);
}

// round 17
// speedup vs baseline: 1.2863x; 1.2863x over previous
#include <cuda_runtime.h>
#include <cstdint>

#define BZf 8
#define Nf 4096
#define CFf 64
#define NSf 1024
#define Kf 64

typedef unsigned long long u64;

// ---------------- scratch (device globals; no allocation) ----------------
__device__ __align__(16) float g_W0f[67 * 64];
__device__ __align__(16) float g_b0f[64];
__device__ __align__(16) float g_W1f[64 * 64];
__device__ __align__(16) float g_b1f[64];
__device__ __align__(16) float g_W2r[2 * 64 * 64];  // [half][ci][cL*4+j] reordered W2
__device__ __align__(16) float g_b2f[128];
__device__ __align__(8) float g_pp[BZf * Nf];
__device__ __align__(16) float g_A[BZf * Nf * 64];  // 8 MB: per-point x·W0'[3:] + b0'
__device__ int   g_knn_idx[BZf * NSf * Kf];         // 2 MB
__device__ float g_knn_dist[BZf * NSf * Kf];        // 2 MB

// ---------------- packed fp32x2 helpers (sm_103a) ----------------
__device__ __forceinline__ void ffma2(u64& acc, u64 a, u64 b) {
    asm("fma.rn.f32x2 %0, %1, %2, %0;" : "+l"(acc) : "l"(a), "l"(b));
}
__device__ __forceinline__ u64 add2(u64 a, u64 b) {
    u64 r;
    asm("add.rn.f32x2 %0, %1, %2;" : "=l"(r) : "l"(a), "l"(b));
    return r;
}
__device__ __forceinline__ u64 mul2(u64 a, u64 b) {
    u64 r;
    asm("mul.rn.f32x2 %0, %1, %2;" : "=l"(r) : "l"(a), "l"(b));
    return r;
}
__device__ __forceinline__ u64 dup2(float v) {
    u64 r;
    unsigned int u = __float_as_uint(v);
    asm("mov.b64 %0, {%1, %1};" : "=l"(r) : "r"(u));
    return r;
}
__device__ __forceinline__ u64 pack2(float lo, float hi) {
    u64 r;
    asm("mov.b64 %0, {%1, %2};" : "=l"(r) : "f"(lo), "f"(hi));
    return r;
}
__device__ __forceinline__ float2 unpack2(u64 v) {
    float2 f;
    asm("mov.b64 {%0, %1}, %2;" : "=f"(f.x), "=f"(f.y) : "l"(v));
    return f;
}

// ---------------- prep: fold BN into weights + per-point squared norms ----------------
__global__ void prep_kernel(const float* pos,
                            const float* W0, const float* b0, const float* gg0, const float* be0,
                            const float* rm0, const float* rv0,
                            const float* W1, const float* b1, const float* gg1, const float* be1,
                            const float* rm1, const float* rv1,
                            const float* W2, const float* b2, const float* gg2, const float* be2,
                            const float* rm2, const float* rv2) {
    int t = blockIdx.x * blockDim.x + threadIdx.x;
    int stride = gridDim.x * blockDim.x;
    for (int i = t; i < 67 * 64; i += stride) {
        int c = i & 63;
        float s = gg0[c] / sqrtf(rv0[c] + 1e-5f);
        g_W0f[i] = W0[i] * s;
    }
    for (int c = t; c < 64; c += stride) {
        float s = gg0[c] / sqrtf(rv0[c] + 1e-5f);
        g_b0f[c] = (b0[c] - rm0[c]) * s + be0[c];
    }
    for (int i = t; i < 64 * 64; i += stride) {
        int c = i & 63;
        float s = gg1[c] / sqrtf(rv1[c] + 1e-5f);
        g_W1f[i] = W1[i] * s;
    }
    for (int c = t; c < 64; c += stride) {
        float s = gg1[c] / sqrtf(rv1[c] + 1e-5f);
        g_b1f[c] = (b1[c] - rm1[c]) * s + be1[c];
    }
    for (int i = t; i < 64 * 128; i += stride) {
        int ci = i >> 7;
        int c = i & 127;
        float s = gg2[c] / sqrtf(rv2[c] + 1e-5f);
        float v = W2[i] * s;
        // reorder: c = cL*8 + half*4 + j  ->  g_W2r[((half*64 + ci)*16 + cL)*4 + j]
        int cL = c >> 3;
        int rem = c & 7;
        int half = rem >> 2;
        int j = rem & 3;
        g_W2r[((half * 64 + ci) * 16 + cL) * 4 + j] = v;
    }
    for (int c = t; c < 128; c += stride) {
        float s = gg2[c] / sqrtf(rv2[c] + 1e-5f);
        g_b2f[c] = (b2[c] - rm2[c]) * s + be2[c];
    }
    for (int i = t; i < BZf * Nf; i += stride) {
        float x = pos[i * 3], y = pos[i * 3 + 1], z = pos[i * 3 + 2];
        g_pp[i] = __fadd_rn(__fadd_rn(__fmul_rn(x, x), __fmul_rn(y, y)), __fmul_rn(z, z));
    }
}

// ---------------- FPS: packed f32x2 distances + REDUX argmax (exact ties) ----------
__global__ __launch_bounds__(1024) void fps_kernel(const float* pos, float* sampled) {
    extern __shared__ unsigned char fsm[];
    float* spx = (float*)fsm;                 // 4096
    float* spy = spx + Nf;                    // 4096
    float* spz = spy + Nf;                    // 4096
    u64* red = (u64*)(spz + Nf);              // 2*32

    int b = blockIdx.x;
    int t = threadIdx.x;
    int lane = t & 31;
    int w = t >> 5;
    float dist[4];
    u64 pxp[2], pyp[2], pzp[2];
    {
        float px[4], py[4], pz[4];
#pragma unroll
        for (int r = 0; r < 4; r++) {
            int i = t + (r << 10);
            const float* p = &pos[(b * Nf + i) * 3];
            float X = p[0], Y = p[1], Z = p[2];
            px[r] = X; py[r] = Y; pz[r] = Z;
            spx[i] = X; spy[i] = Y; spz[i] = Z;
            dist[r] = 1e10f;
        }
        pxp[0] = pack2(px[0], px[1]); pxp[1] = pack2(px[2], px[3]);
        pyp[0] = pack2(py[0], py[1]); pyp[1] = pack2(py[2], py[3]);
        pzp[0] = pack2(pz[0], pz[1]); pzp[1] = pack2(pz[2], pz[3]);
    }
    if (t == 0) {
        const float* p = &pos[b * Nf * 3];
        float* o = &sampled[b * NSf * 3];
        o[0] = p[0]; o[1] = p[1]; o[2] = p[2];
    }
    __syncthreads();
    float cx = spx[0], cy = spy[0], cz = spz[0];
    int parity = 0;

    for (int s = 0; s < NSf - 1; s++) {
        u64 ncx = dup2(-cx), ncy = dup2(-cy), ncz = dup2(-cz);
#pragma unroll
        for (int p = 0; p < 2; p++) {
            u64 dx = add2(pxp[p], ncx);
            u64 dy = add2(pyp[p], ncy);
            u64 dz = add2(pzp[p], ncz);
            u64 xx = mul2(dx, dx);
            u64 yy = mul2(dy, dy);
            u64 zz = mul2(dz, dz);
            u64 dd = add2(add2(xx, yy), zz);
            float2 f = unpack2(dd);
            dist[2 * p] = fminf(dist[2 * p], f.x);
            dist[2 * p + 1] = fminf(dist[2 * p + 1], f.y);
        }
        // max of nonneg floats == max of their bit patterns (alu pipe)
        unsigned int u0 = __float_as_uint(dist[0]), u1 = __float_as_uint(dist[1]);
        unsigned int u2 = __float_as_uint(dist[2]), u3 = __float_as_uint(dist[3]);
        unsigned int mb = max(max(u0, u1), max(u2, u3));
        unsigned int wm = __reduce_max_sync(0xffffffffu, mb);
        // first-match (lowest r) within the thread, ~idx-max across lanes -> global min idx
        unsigned int cand = 0u;
        if (u3 == wm) cand = ~(unsigned int)(t + 3072);
        if (u2 == wm) cand = ~(unsigned int)(t + 2048);
        if (u1 == wm) cand = ~(unsigned int)(t + 1024);
        if (u0 == wm) cand = ~(unsigned int)t;
        unsigned int wi = __reduce_max_sync(0xffffffffu, cand);
        if (lane == 0)
            red[parity * 32 + w] = ((u64)wm << 32) | (u64)wi;
        __syncthreads();
        u64 v = red[parity * 32 + lane];
        unsigned int d2 = (unsigned int)(v >> 32);
        unsigned int i2 = (unsigned int)v;
        unsigned int hi = __reduce_max_sync(0xffffffffu, d2);
        unsigned int c2 = (d2 == hi) ? i2 : 0u;
        unsigned int gi = __reduce_max_sync(0xffffffffu, c2);
        int nidx = (int)(~gi);
        cx = spx[nidx]; cy = spy[nidx]; cz = spz[nidx];
        if (t == 0) {
            float* o = &sampled[(b * NSf + s + 1) * 3];
            o[0] = cx; o[1] = cy; o[2] = cz;
        }
        parity ^= 1;
    }
}

// ---------------- merged precA + kNN (branch by block range) ----------------
#define PKA 2048  // precA blocks (16 rows each)
__global__ __launch_bounds__(256) void pk_kernel(const float* x, const float* pos,
                                                 const float* sampled) {
    extern __shared__ unsigned char smem[];
    int t = threadIdx.x;
    if (blockIdx.x < PKA) {
        // ---- precA: A = x . W0'[3:67] + b0', 16 rows per block ----
        float* sx = (float*)smem;  // 16*64
        int base = blockIdx.x * 16;
        for (int i = t; i < 16 * 64; i += 256) sx[i] = x[base * 64 + i];
        __syncthreads();
        int c = t & 63, rg = t >> 6;  // 4 row-groups x 4 rows
        float bv = g_b0f[c];
        float a0 = bv, a1 = bv, a2 = bv, a3 = bv;
        const float* sxr = &sx[rg * 4 * 64];
#pragma unroll 8
        for (int i = 0; i < 64; i++) {
            float wv = g_W0f[(3 + i) * 64 + c];
            a0 = fmaf(sxr[i], wv, a0);
            a1 = fmaf(sxr[64 + i], wv, a1);
            a2 = fmaf(sxr[128 + i], wv, a2);
            a3 = fmaf(sxr[192 + i], wv, a3);
        }
        int r0 = base + rg * 4;
        g_A[(r0 + 0) * 64 + c] = a0;
        g_A[(r0 + 1) * 64 + c] = a1;
        g_A[(r0 + 2) * 64 + c] = a2;
        g_A[(r0 + 3) * 64 + c] = a3;
        return;
    }
    // ---- kNN top-64: packed paired d^2, two passes (no sd buffer -> 6 blocks/SM) ----
    u64* cand = (u64*)smem;                         // 4096 u64 = 32KB
    int* scnt = (int*)(smem + 4096 * 8);            // 6 ints
    __shared__ float cxs, cys, czs, sss;
    int g = blockIdx.x - PKA;
    int b = g >> 10;
    if (t == 0) {
        float cx = sampled[g * 3], cy = sampled[g * 3 + 1], cz = sampled[g * 3 + 2];
        cxs = cx; cys = cy; czs = cz;
        sss = __fadd_rn(__fadd_rn(__fmul_rn(cx, cx), __fmul_rn(cy, cy)), __fmul_rn(cz, cz));
    }
    if (t < 6) scnt[t] = 0;
    __syncthreads();
    float sx = cxs, sy = cys, sz = czs, ss = sss;
    const float T0L = 0.18f * 0.18f * 0.99999f, T0H = 0.18f * 0.18f * 1.00001f;
    const float T1L = 0.25f * 0.25f * 0.99999f, T1H = 0.25f * 0.25f * 1.00001f;
    const float T2L = 0.35f * 0.35f * 0.99999f, T2H = 0.35f * 0.35f * 1.00001f;
    const float T3L = 0.55f * 0.55f * 0.99999f, T3H = 0.55f * 0.55f * 1.00001f;
    const float2* pb2 = (const float2*)&pos[b * Nf * 3];
    const float2* ppb2 = (const float2*)&g_pp[b * Nf];
    u64 sx2 = dup2(sx), sy2 = dup2(sy), sz2 = dup2(sz);
    u64 ss2 = dup2(ss), n2 = dup2(-2.0f);
    // pass 1: count (packed paired d^2; bit-exact vs reference formula)
    {
        int c0 = 0, c1 = 0, c2 = 0, c3 = 0;
        for (int q = t; q < Nf / 2; q += 256) {
            float2 q0 = pb2[3 * q];          // X0 Y0
            float2 q1 = pb2[3 * q + 1];      // Z0 X1
            float2 q2 = pb2[3 * q + 2];      // Y1 Z1
            u64 xs = pack2(q0.x, q1.y);
            u64 ys = pack2(q0.y, q2.x);
            u64 zs = pack2(q1.x, q2.y);
            float2 ppv = ppb2[q];
            u64 pp2 = pack2(ppv.x, ppv.y);
            u64 dot = add2(add2(mul2(sx2, xs), mul2(sy2, ys)), mul2(sz2, zs));
            u64 d2p = add2(add2(ss2, pp2), mul2(n2, dot));
            float2 dv = unpack2(d2p);
            c0 += (dv.x <= T0L) + (dv.y <= T0L);
            c1 += (dv.x <= T1L) + (dv.y <= T1L);
            c2 += (dv.x <= T2L) + (dv.y <= T2L);
            c3 += (dv.x <= T3L) + (dv.y <= T3L);
        }
        atomicAdd(&scnt[0], c0);
        atomicAdd(&scnt[1], c1);
        atomicAdd(&scnt[2], c2);
        atomicAdd(&scnt[3], c3);
    }
    __syncthreads();
    float thrsq;
    if (scnt[0] >= Kf) thrsq = T0H;
    else if (scnt[1] >= Kf) thrsq = T1H;
    else if (scnt[2] >= Kf) thrsq = T2H;
    else if (scnt[3] >= Kf) thrsq = T3H;
    else thrsq = 1e30f;
    // pass 2: recompute d^2 (identical ops -> identical bits) and collect survivors
    for (int q = t; q < Nf / 2; q += 256) {
        float2 q0 = pb2[3 * q];
        float2 q1 = pb2[3 * q + 1];
        float2 q2 = pb2[3 * q + 2];
        u64 xs = pack2(q0.x, q1.y);
        u64 ys = pack2(q0.y, q2.x);
        u64 zs = pack2(q1.x, q2.y);
        float2 ppv = ppb2[q];
        u64 pp2 = pack2(ppv.x, ppv.y);
        u64 dot = add2(add2(mul2(sx2, xs), mul2(sy2, ys)), mul2(sz2, zs));
        u64 d2p = add2(add2(ss2, pp2), mul2(n2, dot));
        float2 dv = unpack2(d2p);
        if (dv.x <= thrsq) {
            float d = sqrtf(fmaxf(dv.x, 0.0f));  // exact same expr as reference path
            int slot = atomicAdd(&scnt[5], 1);
            cand[slot] = ((u64)__float_as_uint(d) << 32) | (unsigned int)(2 * q);
        }
        if (dv.y <= thrsq) {
            float d = sqrtf(fmaxf(dv.y, 0.0f));
            int slot = atomicAdd(&scnt[5], 1);
            cand[slot] = ((u64)__float_as_uint(d) << 32) | (unsigned int)(2 * q + 1);
        }
    }
    __syncthreads();
    int cnt = scnt[5];
    int P = 128;
    while (P < cnt) P <<= 1;
    for (int i = t; i < P; i += 256)
        if (i >= cnt) cand[i] = 0xffffffffffffffffull;
    __syncthreads();
    for (int k2 = 2; k2 <= P; k2 <<= 1) {
        for (int j = k2 >> 1; j > 0; j >>= 1) {
            for (int i = t; i < P; i += 256) {
                int ij = i ^ j;
                if (ij > i) {
                    u64 a = cand[i], bb = cand[ij];
                    bool up = ((i & k2) == 0);
                    if ((a > bb) == up) { cand[i] = bb; cand[ij] = a; }
                }
            }
            __syncthreads();
        }
    }
    if (t < Kf) {
        u64 key = cand[t];
        g_knn_idx[g * Kf + t] = (int)(key & 0xffffffffull);
        g_knn_dist[g * Kf + t] = __uint_as_float((unsigned int)(key >> 32));
    }
}

// ---- fused MLP (FFMA2; W1+W2 via LDG float4) + masked max-pool; 8 blocks/SM ----
#define AKS 68  // activation row stride ([c][k] layout), 16B-aligned rows
__global__ __launch_bounds__(128, 8) void mlp_kernel(const float* pos, const float* sampled,
                                                     float* out) {
    extern __shared__ unsigned char smem[];
    float* act = (float*)smem;             // 64*68 (layer1 out -> layer2 out -> pmax alias)
    float* sB1 = act + 64 * AKS;           // 64
    float* sB2 = sB1 + 64;                 // 128
    float* sdpx = sB2 + 128;               // 64
    float* sdpy = sdpx + 64;               // 64
    float* sdpz = sdpy + 64;               // 64
    int* sidx = (int*)(sdpz + 64);         // 64
    int* smask = sidx + 64;                // 64
    float* pmax = act;                     // 8*128, aliased into act after barrier

    int g = blockIdx.x;
    int b = g >> 10;
    int t = threadIdx.x;
    int w = t >> 5, lane = t & 31;
    int ksub = lane >> 4;                  // 0/1
    int k0 = w * 16 + ksub * 8;            // this thread's 8 k's (layers 2/3)
    int cL = lane & 15;

    if (t < 64) sB1[t] = g_b1f[t];
    if (t < 128) sB2[t] = g_b2f[t];
    if (t < 64) {
        int idx = g_knn_idx[g * Kf + t];
        float d = g_knn_dist[g * Kf + t];
        const float* p = &pos[(b * Nf + idx) * 3];
        float ccx = sampled[g * 3], ccy = sampled[g * 3 + 1], ccz = sampled[g * 3 + 2];
        sdpx[t] = p[0] - ccx;
        sdpy[t] = p[1] - ccy;
        sdpz[t] = p[2] - ccz;
        sidx[t] = idx;
        smask[t] = (d <= 0.2f) ? 1 : 0;
    }
    __syncthreads();

    // layer 1 (input 67 -> 64): thread owns (c, one 32-k half), even k-pairs.
    {
        int c = t & 63;
        int h = t >> 6;                    // 0/1
        int kb = h * 32;
        float w0 = g_W0f[c], w1 = g_W0f[64 + c], w2 = g_W0f[128 + c];
        const float* Ab = &g_A[(size_t)b * Nf * 64 + c];
#pragma unroll 4
        for (int i = 0; i < 16; i++) {
            int k = kb + 2 * i;
            int2 si = *(const int2*)&sidx[k];
            float a0 = Ab[si.x * 64];
            float a1 = Ab[si.y * 64];
            float2 dx2 = *(const float2*)&sdpx[k];
            float2 dy2 = *(const float2*)&sdpy[k];
            float2 dz2 = *(const float2*)&sdpz[k];
            float z0 = fmaf(dx2.x, w0, a0);
            z0 = fmaf(dy2.x, w1, z0);
            z0 = fmaf(dz2.x, w2, z0);
            float z1 = fmaf(dx2.y, w0, a1);
            z1 = fmaf(dy2.y, w1, z1);
            z1 = fmaf(dz2.y, w2, z1);
            float2 r;
            r.x = fmaxf(z0, 0.0f);
            r.y = fmaxf(z1, 0.0f);
            *(float2*)&act[c * AKS + k] = r;
        }
    }
    __syncthreads();

    // layer 2 (64 -> 64): thread tile 8k x 4c; act via ulonglong2, W1 via LDG (L1-resident)
    u64 acc2[4][4];
    {
        const float4* W1v = (const float4*)g_W1f;  // 16 float4 per ci row
#pragma unroll
        for (int j = 0; j < 4; j++)
#pragma unroll
            for (int q = 0; q < 4; q++) acc2[j][q] = 0ull;
        for (int ci = 0; ci < 64; ci++) {
            ulonglong2 va = *(const ulonglong2*)&act[ci * AKS + k0];
            ulonglong2 vb = *(const ulonglong2*)&act[ci * AKS + k0 + 4];
            u64 a0 = va.x, a1 = va.y, a2 = vb.x, a3 = vb.y;
            float4 wv = __ldg(&W1v[ci * 16 + cL]);
            u64 w0 = dup2(wv.x), w1 = dup2(wv.y), w2 = dup2(wv.z), w3 = dup2(wv.w);
            ffma2(acc2[0][0], a0, w0); ffma2(acc2[1][0], a1, w0);
            ffma2(acc2[2][0], a2, w0); ffma2(acc2[3][0], a3, w0);
            ffma2(acc2[0][1], a0, w1); ffma2(acc2[1][1], a1, w1);
            ffma2(acc2[2][1], a2, w1); ffma2(acc2[3][1], a3, w1);
            ffma2(acc2[0][2], a0, w2); ffma2(acc2[1][2], a1, w2);
            ffma2(acc2[2][2], a2, w2); ffma2(acc2[3][2], a3, w2);
            ffma2(acc2[0][3], a0, w3); ffma2(acc2[1][3], a1, w3);
            ffma2(acc2[2][3], a2, w3); ffma2(acc2[3][3], a3, w3);
        }
    }
    __syncthreads();  // all reads of layer-1 act done; safe to overwrite
    {
        int cc0 = cL * 4;
#pragma unroll
        for (int cq = 0; cq < 4; cq++) {
            float bb = sB1[cc0 + cq];
#pragma unroll
            for (int kp = 0; kp < 4; kp++) {
                float2 v = unpack2(acc2[kp][cq]);
                float2 r;
                r.x = fmaxf(v.x + bb, 0.0f);
                r.y = fmaxf(v.y + bb, 0.0f);
                *(float2*)&act[(cc0 + cq) * AKS + k0 + 2 * kp] = r;
            }
        }
    }
    __syncthreads();

    // layer 3 (64 -> 128) + masked max pool: two passes of 4 channels
    // W2 via reordered g_W2r; act via ulonglong2
    float mres[8];
    const float4* W2rv = (const float4*)g_W2r;  // [(half*64+ci)*16 + cL]
#pragma unroll 1
    for (int half = 0; half < 2; half++) {
        int cc0 = cL * 8 + half * 4;
        u64 acc[4][4];
#pragma unroll
        for (int j = 0; j < 4; j++)
#pragma unroll
            for (int q = 0; q < 4; q++) acc[j][q] = 0ull;
#pragma unroll 2
        for (int ci = 0; ci < 64; ci++) {
            ulonglong2 va = *(const ulonglong2*)&act[ci * AKS + k0];
            ulonglong2 vb = *(const ulonglong2*)&act[ci * AKS + k0 + 4];
            u64 a0 = va.x, a1 = va.y, a2 = vb.x, a3 = vb.y;
            float4 wv = __ldg(&W2rv[(half * 64 + ci) * 16 + cL]);
            u64 w0 = dup2(wv.x), w1 = dup2(wv.y), w2 = dup2(wv.z), w3 = dup2(wv.w);
            ffma2(acc[0][0], a0, w0); ffma2(acc[1][0], a1, w0);
            ffma2(acc[2][0], a2, w0); ffma2(acc[3][0], a3, w0);
            ffma2(acc[0][1], a0, w1); ffma2(acc[1][1], a1, w1);
            ffma2(acc[2][1], a2, w1); ffma2(acc[3][1], a3, w1);
            ffma2(acc[0][2], a0, w2); ffma2(acc[1][2], a1, w2);
            ffma2(acc[2][2], a2, w2); ffma2(acc[3][2], a3, w2);
            ffma2(acc[0][3], a0, w3); ffma2(acc[1][3], a1, w3);
            ffma2(acc[2][3], a2, w3); ffma2(acc[3][3], a3, w3);
        }
#pragma unroll
        for (int cq = 0; cq < 4; cq++) {
            float bb = sB2[cc0 + cq];
            float m = -1e8f;
#pragma unroll
            for (int kp = 0; kp < 4; kp++) {
                float2 v = unpack2(acc[kp][cq]);
                float h0 = fmaxf(v.x + bb, 0.0f);
                float h1 = fmaxf(v.y + bb, 0.0f);
                float q0 = smask[k0 + 2 * kp] ? h0 : -1e8f;
                float q1 = smask[k0 + 2 * kp + 1] ? h1 : -1e8f;
                m = fmaxf(m, fmaxf(q0, q1));
            }
            mres[half * 4 + cq] = m;
        }
    }
    __syncthreads();  // all act reads done; alias pmax onto act
    {
        int base = (w * 2 + ksub) * 128 + cL * 8;
#pragma unroll
        for (int q = 0; q < 8; q++) pmax[base + q] = mres[q];
    }
    __syncthreads();
    if (t < 128) {
        float m = pmax[t];
#pragma unroll
        for (int q = 1; q < 8; q++) m = fmaxf(m, pmax[q * 128 + t]);
        out[g * 128 + t] = m;
    }
}

// ---------------- launch ----------------
extern "C" void kernel_launch(void* const* d_in, const int* in_sizes, int n_in,
                              void* d_out, int out_size) {
    (void)in_sizes; (void)n_in; (void)out_size;
    const float* x = (const float*)d_in[0];
    const float* pos = (const float*)d_in[1];
    const float* W0 = (const float*)d_in[2];
    const float* b0 = (const float*)d_in[3];
    const float* gg0 = (const float*)d_in[4];
    const float* be0 = (const float*)d_in[5];
    const float* rm0 = (const float*)d_in[6];
    const float* rv0 = (const float*)d_in[7];
    const float* W1 = (const float*)d_in[8];
    const float* b1 = (const float*)d_in[9];
    const float* gg1 = (const float*)d_in[10];
    const float* be1 = (const float*)d_in[11];
    const float* rm1 = (const float*)d_in[12];
    const float* rv1 = (const float*)d_in[13];
    const float* W2 = (const float*)d_in[14];
    const float* b2 = (const float*)d_in[15];
    const float* gg2 = (const float*)d_in[16];
    const float* be2 = (const float*)d_in[17];
    const float* rm2 = (const float*)d_in[18];
    const float* rv2 = (const float*)d_in[19];

    float* out = (float*)d_out;
    float* sampled = out + (size_t)BZf * NSf * 128;

    const int pk_smem = 4096 * 8 + 32;              // 32800 -> 6 blocks/SM
    const int mlp_smem = (64 * AKS + 64 + 128 + 64 * 5) * 4;  // 19456
    const int fps_smem = Nf * 3 * 4 + 2 * 32 * 8;   // 49664
    cudaFuncSetAttribute(pk_kernel, cudaFuncAttributeMaxDynamicSharedMemorySize, pk_smem);
    cudaFuncSetAttribute(mlp_kernel, cudaFuncAttributeMaxDynamicSharedMemorySize, mlp_smem);
    cudaFuncSetAttribute(fps_kernel, cudaFuncAttributeMaxDynamicSharedMemorySize, fps_smem);

    prep_kernel<<<64, 256>>>(pos,
                             W0, b0, gg0, be0, rm0, rv0,
                             W1, b1, gg1, be1, rm1, rv1,
                             W2, b2, gg2, be2, rm2, rv2);
    fps_kernel<<<BZf, 1024, fps_smem>>>(pos, sampled);
    pk_kernel<<<PKA + BZf * NSf, 256, pk_smem>>>(x, pos, sampled);
    mlp_kernel<<<BZf * NSf, 128, mlp_smem>>>(pos, sampled, out);
}